// round 17
// baseline (speedup 1.0000x reference)
#include <cuda_runtime.h>
#include <cstdint>

// ---------------- constants ----------------
#define TT    9
#define BB    8
#define CC    256
#define HWHW  3136
#define PIX   16
#define NTHREADS 1024
#define TILES_PER_B 196          // 3136/16
#define NTILES 1568              // total 16-px tiles
#define GRID  148                // persistent, 1 CTA/SM

#define H0_T  4                  // t = 0..3  (A half)
#define H1_T  5                  // t = 4..8  (B half)
#define A_FLOATS (H0_T*CC*PIX)   // 16384 floats = 65536 B
#define B_FLOATS (H1_T*CC*PIX)   // 20480 floats = 81920 B

// SMEM layout (float offsets)
#define OFF_A    0
#define OFF_B    (A_FLOATS)                  // 16384
#define OFF_PART (A_FLOATS + B_FLOATS)       // 36864  [32 warps][144]
#define OFF_SCOR (OFF_PART + 32*144)         // 41472  [144]
#define SMEM_FLOATS (OFF_SCOR + 144)
#define SMEM_BYTES  (SMEM_FLOATS * 4)        // 166464 B

// work-stealing counter (reset each launch by tfma_reset_kernel)
__device__ int g_tile_ctr;

__global__ void tfma_reset_kernel() { g_tile_ctr = 0; }

// Coalesced half loader: thread = (q = tid&3, rb = tid>>2); row (t0+j, rb)
// is 16 floats (64 B); this thread copies its 16 B quarter for nt t-slices.
// A warp covers 8 consecutive c-rows -> 8 lines/warp-op.
__device__ __forceinline__ void cp_half(uint32_t dst_bytes,
                                        const float* __restrict__ src, // seq + b*CC*HW + pix0
                                        int q, int rb, int t0, int nt)
{
    const float* g = src + (size_t)t0 * BB * CC * HWHW + (size_t)rb * HWHW + q * 4;
    uint32_t s = dst_bytes + (uint32_t)((rb * PIX + q * 4) * 4);
    #pragma unroll
    for (int j = 0; j < nt; ++j) {
        asm volatile("cp.async.cg.shared.global [%0], [%1], 16;\n"
                     :: "r"(s), "l"(g) : "memory");
        g += (size_t)BB * CC * HWHW;    // next t
        s += CC * PIX * 4;              // 16384 B per t-slab
    }
}

#define COMMIT() asm volatile("cp.async.commit_group;\n" ::: "memory")
#define WAITG(n) asm volatile("cp.async.wait_group %0;\n" :: "n"(n) : "memory")

// ---------------- main kernel ----------------
__global__ __launch_bounds__(NTHREADS, 1)
void tfma_r15_kernel(const float* __restrict__ seq,
                     const float* __restrict__ wptr,
                     const float* __restrict__ bptr,   // unused: softmax shift-invariant
                     const float* __restrict__ gptr,
                     float* __restrict__ out)
{
    extern __shared__ float sm[];
    float* part = sm + OFF_PART;
    float* scor = sm + OFF_SCOR;
    __shared__ int s_next;
    const uint32_t smem_base = (uint32_t)__cvta_generic_to_shared(sm);
    const uint32_t dstA = smem_base;
    const uint32_t dstB = smem_base + A_FLOATS * 4;

    const int tid  = threadIdx.x;
    const int lane = tid & 31;
    const int wrp  = tid >> 5;
    const int p    = tid & (PIX - 1);   // 0..15
    const int cg   = tid >> 4;          // 0..63
    const int q    = tid & 3;           // load quarter
    const int rb   = tid >> 2;          // load row (c) 0..255

    // w_other only: w_center + bias shift all t equally -> softmax-invariant.
    float wot[4];
    #pragma unroll
    for (int ci = 0; ci < 4; ++ci)
        wot[ci] = wptr[CC + cg + (ci << 6)];
    const float gamma = gptr[0];
    (void)bptr;

    // ---- steal first tile ----
    if (tid == 0) s_next = atomicAdd(&g_tile_ctr, 1);
    __syncthreads();
    int g = s_next;
    if (g >= NTILES) return;            // cannot happen at GRID=148, kept for safety

    // prologue: A(g), B(g)
    {
        const float* src = seq + (size_t)(g / TILES_PER_B) * CC * HWHW
                               + (g % TILES_PER_B) * PIX;
        cp_half(dstA, src, q, rb, 0, H0_T);
        COMMIT();
        cp_half(dstB, src, q, rb, H0_T, H1_T);
        COMMIT();
    }

    #pragma unroll 1
    while (g < NTILES) {
        const int bidx = g / TILES_PER_B;
        const int pix0 = (g % TILES_PER_B) * PIX;

        float rv[4][TT];
        float acc[TT];
        #pragma unroll
        for (int t = 0; t < TT; ++t) acc[t] = 0.f;

        // ---- wait A(k): exactly one group (B(k)) may remain pending ----
        WAITG(1);
        __syncthreads();                       // bar0: A visible to all
        if (tid == 0) s_next = atomicAdd(&g_tile_ctr, 1);   // steal next (hidden)

        #pragma unroll
        for (int ci = 0; ci < 4; ++ci) {
            const int c = cg + (ci << 6);
            #pragma unroll
            for (int t = 0; t < H0_T; ++t) {
                rv[ci][t] = sm[(t * CC + c) * PIX + p];
                acc[t] = fmaf(rv[ci][t], wot[ci], acc[t]);
            }
        }

        // ---- wait B(k) ----
        WAITG(0);
        __syncthreads();                       // bar1: A consumed + B visible + s_next visible

        const int gn = s_next;
        const bool more = (gn < NTILES);
        const float* nsrc = seq + (size_t)(gn / TILES_PER_B) * CC * HWHW
                                + (gn % TILES_PER_B) * PIX;

        if (more) cp_half(dstA, nsrc, q, rb, 0, H0_T);   // refill A(gn)
        COMMIT();

        #pragma unroll
        for (int ci = 0; ci < 4; ++ci) {
            const int c = cg + (ci << 6);
            #pragma unroll
            for (int t = H0_T; t < TT; ++t) {
                rv[ci][t] = sm[OFF_B + ((t - H0_T) * CC + c) * PIX + p];
                acc[t] = fmaf(rv[ci][t], wot[ci], acc[t]);
            }
        }
        // warp partials: xor16 combines the warp's two c-groups (same p)
        #pragma unroll
        for (int t = 0; t < TT; ++t)
            acc[t] += __shfl_xor_sync(0xffffffffu, acc[t], 16);
        if (lane < PIX) {
            #pragma unroll
            for (int t = 0; t < TT; ++t)
                part[wrp * 144 + t * PIX + lane] = acc[t];
        }
        __syncthreads();                       // bar2: B consumed + partials visible

        if (more) cp_half(dstB, nsrc, q, rb, H0_T, H1_T);  // refill B(gn)
        COMMIT();

        // ---- cross-warp reduce: 144 threads ----
        if (tid < 144) {
            float s = 0.f;
            #pragma unroll
            for (int w = 0; w < 32; ++w) s += part[w * 144 + tid];
            scor[tid] = s;
        }
        __syncthreads();                       // bar3: scor visible

        // ---- softmax (shift-free) + attended sum + residual ----
        {
            float a[TT];
            float m = -1e30f;
            #pragma unroll
            for (int t = 0; t < TT; ++t) {
                a[t] = scor[t * PIX + p];
                m = fmaxf(m, a[t]);
            }
            float sum = 0.f;
            #pragma unroll
            for (int t = 0; t < TT; ++t) {
                a[t] = __expf(a[t] - m);
                sum += a[t];
            }
            const float inv = 1.f / sum;
            #pragma unroll
            for (int t = 0; t < TT; ++t) a[t] *= inv;

            float* ob = out + (size_t)bidx * CC * HWHW + pix0 + p;
            #pragma unroll
            for (int ci = 0; ci < 4; ++ci) {
                const int c = cg + (ci << 6);
                float s = 0.f;
                #pragma unroll
                for (int t = 0; t < TT; ++t)
                    s = fmaf(a[t], rv[ci][t], s);
                ob[(size_t)c * HWHW] = rv[ci][TT / 2] + gamma * s;
            }
        }

        g = gn;
        // Reuse safety identical to R12 (bar positions unchanged):
        //  - part(next) written after bar1(next) > bar3(cur) >= reduce reads.
        //  - scor(next) written after bar2(next) > bar0(next) >= softmax reads.
        //  - A(next) issued after bar1(cur); B(next) after bar2(cur).
        //  - exactly 2 groups committed per iteration -> WAITG counts exact.
        //  - s_next: written by tid0 after bar0, read by all after bar1;
        //    next overwrite is after the following bar0 -> ordered.
    }
}

extern "C" void kernel_launch(void* const* d_in, const int* in_sizes, int n_in,
                              void* d_out, int out_size)
{
    (void)in_sizes; (void)n_in; (void)out_size;
    const float* seq   = (const float*)d_in[0];
    const float* w     = (const float*)d_in[1];
    const float* bv    = (const float*)d_in[2];
    const float* gamma = (const float*)d_in[3];
    float* out = (float*)d_out;

    tfma_reset_kernel<<<1, 1>>>();
    cudaFuncSetAttribute(tfma_r15_kernel,
                         cudaFuncAttributeMaxDynamicSharedMemorySize, SMEM_BYTES);
    tfma_r15_kernel<<<GRID, NTHREADS, SMEM_BYTES>>>(seq, w, bv, gamma, out);
}